// round 8
// baseline (speedup 1.0000x reference)
#include <cuda_runtime.h>
#include <cuda_bf16.h>
#include <cstdint>

#define NNODES 100000
#define NEDGES 1600000
#define DIM    128
#define SCANB  1024
#define NBLK   ((NNODES + SCANB - 1) / SCANB)   // 98

typedef unsigned long long u64;

// ---------------- scratch (alloc-free rule: __device__ globals) -------------
// NOTE: g_deg relies on static zero-init for the FIRST call; fill_kernel
// re-zeroes it at the end of every call, restoring the invariant for replays.
__device__ float g_agg[(size_t)NNODES * DIM];
__device__ int   g_deg[NNODES];
__device__ int   g_incl[NNODES];
__device__ int   g_off[NNODES + 1];
__device__ int   g_cur[NNODES];
__device__ int   g_csr[NEDGES];
__device__ int   g_bsum[128];
__device__ int   g_bofs[128];

// ---------------------------------------------------------------------------
// packed fp32x2 helpers (Blackwell: ptxas never auto-fuses these)
// ---------------------------------------------------------------------------
__device__ __forceinline__ u64 fadd2(u64 a, u64 b) {
    u64 d;
    asm("add.rn.f32x2 %0, %1, %2;" : "=l"(d) : "l"(a), "l"(b));
    return d;
}
__device__ __forceinline__ u64 ffma2(u64 a, u64 b, u64 c) {
    u64 d;
    asm("fma.rn.f32x2 %0, %1, %2, %3;" : "=l"(d) : "l"(a), "l"(b), "l"(c));
    return d;
}
__device__ __forceinline__ u64 pk2(float lo, float hi) {
    u64 r;
    asm("mov.b64 %0, {%1, %2};" : "=l"(r) : "f"(lo), "f"(hi));
    return r;
}
__device__ __forceinline__ float2 up2(u64 v) {
    float2 r;
    asm("mov.b64 {%0, %1}, %2;" : "=f"(r.x), "=f"(r.y) : "l"(v));
    return r;
}

// ---------------------------------------------------------------------------
// CSR build
// ---------------------------------------------------------------------------
__global__ void hist_kernel(const int* __restrict__ ei) {
    int e = blockIdx.x * blockDim.x + threadIdx.x;
    if (e < NEDGES) atomicAdd(&g_deg[__ldg(ei + NEDGES + e)], 1);
}

__global__ void scan1_kernel() {
    __shared__ int sm[SCANB];
    int i = blockIdx.x * SCANB + threadIdx.x;
    int v = (i < NNODES) ? g_deg[i] : 0;
    sm[threadIdx.x] = v;
    __syncthreads();
#pragma unroll
    for (int ofs = 1; ofs < SCANB; ofs <<= 1) {
        int t = (threadIdx.x >= ofs) ? sm[threadIdx.x - ofs] : 0;
        __syncthreads();
        sm[threadIdx.x] += t;
        __syncthreads();
    }
    if (i < NNODES) g_incl[i] = sm[threadIdx.x];
    if (threadIdx.x == SCANB - 1) g_bsum[blockIdx.x] = sm[SCANB - 1];
}

__global__ void scan2_kernel() {
    __shared__ int sm[128];
    int t = threadIdx.x;
    int v = (t < NBLK) ? g_bsum[t] : 0;
    sm[t] = v;
    __syncthreads();
#pragma unroll
    for (int ofs = 1; ofs < 128; ofs <<= 1) {
        int u = (t >= ofs) ? sm[t - ofs] : 0;
        __syncthreads();
        sm[t] += u;
        __syncthreads();
    }
    if (t < NBLK) g_bofs[t] = sm[t] - v;    // exclusive
}

__global__ void scan3_kernel() {
    int i = blockIdx.x * blockDim.x + threadIdx.x;
    if (i < NNODES) {
        int off = g_incl[i] - g_deg[i] + g_bofs[i >> 10];
        g_off[i] = off;
        g_cur[i] = off;
    }
    if (i == 0) g_off[NNODES] = NEDGES;
}

__global__ void fill_kernel(const int* __restrict__ ei) {
    int e = blockIdx.x * blockDim.x + threadIdx.x;
    if (e < NEDGES) {
        int dst = __ldg(ei + NEDGES + e);
        int p = atomicAdd(&g_cur[dst], 1);
        g_csr[p] = __ldg(ei + e);
    }
    // restore g_deg = 0 for the next call (nobody reads g_deg after scan3)
    if (e < NNODES) g_deg[e] = 0;
}

// ---------------------------------------------------------------------------
// Aggregation: one warp per destination node; lane l owns dims [4l, 4l+4).
// 8-deep explicit load batching (MLP 8) + dual packed-f32x2 accumulator
// chains. Self term folded into chain-0 init.
// ---------------------------------------------------------------------------
__global__ __launch_bounds__(256)
void agg_kernel(const float* __restrict__ x) {
    int w    = (blockIdx.x * blockDim.x + threadIdx.x) >> 5;
    int lane = threadIdx.x & 31;
    if (w >= NNODES) return;

    const float4* X = reinterpret_cast<const float4*>(x);
    int s = g_off[w];
    int e = g_off[w + 1];

    float4 self = __ldg(X + (size_t)w * 32 + lane);
    u64 c0a = pk2(self.x, self.y), c0b = pk2(self.z, self.w);
    u64 c1a = 0, c1b = 0;   // packed zeros

    for (int base = s; base < e; base += 32) {
        int idx = base + lane;
        int my  = (idx < e) ? __ldg(g_csr + idx) : 0;
        int nv  = min(32, e - base);

        int j = 0;
        for (; j + 8 <= nv; j += 8) {
            float4 v[8];
#pragma unroll
            for (int t = 0; t < 8; ++t) {
                int src = __shfl_sync(0xffffffffu, my, j + t);
                v[t] = __ldg(X + (size_t)src * 32 + lane);
            }
#pragma unroll
            for (int t = 0; t < 8; t += 2) {
                c0a = fadd2(c0a, pk2(v[t].x, v[t].y));
                c0b = fadd2(c0b, pk2(v[t].z, v[t].w));
                c1a = fadd2(c1a, pk2(v[t + 1].x, v[t + 1].y));
                c1b = fadd2(c1b, pk2(v[t + 1].z, v[t + 1].w));
            }
        }
        for (; j < nv; ++j) {
            int src  = __shfl_sync(0xffffffffu, my, j);
            float4 v = __ldg(X + (size_t)src * 32 + lane);
            if (j & 1) {
                c1a = fadd2(c1a, pk2(v.x, v.y));
                c1b = fadd2(c1b, pk2(v.z, v.w));
            } else {
                c0a = fadd2(c0a, pk2(v.x, v.y));
                c0b = fadd2(c0b, pk2(v.z, v.w));
            }
        }
    }

    float2 ra = up2(fadd2(c0a, c1a));
    float2 rb = up2(fadd2(c0b, c1b));
    reinterpret_cast<float4*>(g_agg)[(size_t)w * 32 + lane] =
        make_float4(ra.x, ra.y, rb.x, rb.y);
}

// ---------------------------------------------------------------------------
// GEMM: out[n][o] = bias[o] + sum_k H[n][k] * W[o][k]   (packed f32x2 FMA)
// ---------------------------------------------------------------------------
__global__ __launch_bounds__(256, 2)
void gemm_kernel(const float* __restrict__ H,
                 const float* __restrict__ W,
                 const float* __restrict__ bias,
                 float* __restrict__ out) {
    extern __shared__ float sm[];
    float* Wt = sm;               // [128][128]  Wt[k*128 + o]
    float* HT = sm + DIM * DIM;   // [128][64]   HT[k*64 + n]

    const int tid   = threadIdx.x;
    const int node0 = blockIdx.x * 64;

    for (int i = tid; i < DIM * DIM / 4; i += 256) {
        int o = (i * 4) / DIM;
        int k = (i * 4) % DIM;
        float4 w = __ldg(reinterpret_cast<const float4*>(W) + i);
        Wt[(k + 0) * DIM + o] = w.x;
        Wt[(k + 1) * DIM + o] = w.y;
        Wt[(k + 2) * DIM + o] = w.z;
        Wt[(k + 3) * DIM + o] = w.w;
    }
    for (int i = tid; i < 64 * DIM / 4; i += 256) {
        int n = (i * 4) / DIM;
        int k = (i * 4) % DIM;
        int node = node0 + n;
        float4 h = make_float4(0.f, 0.f, 0.f, 0.f);
        if (node < NNODES)
            h = __ldg(reinterpret_cast<const float4*>(H) + ((size_t)node * DIM + k) / 4);
        HT[(k + 0) * 64 + n] = h.x;
        HT[(k + 1) * 64 + n] = h.y;
        HT[(k + 2) * 64 + n] = h.z;
        HT[(k + 3) * 64 + n] = h.w;
    }
    __syncthreads();

    const int tx = tid & 15;
    const int ty = tid >> 4;
    const int o0 = tx * 8;
    const int n0 = ty * 4;

    u64 acc[4][4];
    {
        float4 b0 = __ldg(reinterpret_cast<const float4*>(bias + o0));
        float4 b1 = __ldg(reinterpret_cast<const float4*>(bias + o0 + 4));
        u64 bp[4] = { pk2(b0.x, b0.y), pk2(b0.z, b0.w),
                      pk2(b1.x, b1.y), pk2(b1.z, b1.w) };
#pragma unroll
        for (int i = 0; i < 4; ++i)
#pragma unroll
            for (int j = 0; j < 4; ++j) acc[i][j] = bp[j];
    }

#pragma unroll 4
    for (int k = 0; k < DIM; ++k) {
        float4 av = *reinterpret_cast<const float4*>(&HT[k * 64 + n0]);
        float4 w0 = *reinterpret_cast<const float4*>(&Wt[k * DIM + o0]);
        float4 w1 = *reinterpret_cast<const float4*>(&Wt[k * DIM + o0 + 4]);
        // pairs of adjacent float4 components -> register-pair aliasing (free)
        u64 wp[4] = { pk2(w0.x, w0.y), pk2(w0.z, w0.w),
                      pk2(w1.x, w1.y), pk2(w1.z, w1.w) };
        u64 ap[4] = { pk2(av.x, av.x), pk2(av.y, av.y),
                      pk2(av.z, av.z), pk2(av.w, av.w) };
#pragma unroll
        for (int i = 0; i < 4; ++i)
#pragma unroll
            for (int j = 0; j < 4; ++j)
                acc[i][j] = ffma2(ap[i], wp[j], acc[i][j]);
    }

#pragma unroll
    for (int i = 0; i < 4; ++i) {
        int node = node0 + n0 + i;
        if (node < NNODES) {
            ulonglong2* orow = reinterpret_cast<ulonglong2*>(out + (size_t)node * DIM + o0);
            orow[0] = make_ulonglong2(acc[i][0], acc[i][1]);
            orow[1] = make_ulonglong2(acc[i][2], acc[i][3]);
        }
    }
}

// ---------------------------------------------------------------------------
// Launch. Output tuple (out, hid): d_out[0:N*D)=out, d_out[N*D:2N*D)=hid.
// ---------------------------------------------------------------------------
extern "C" void kernel_launch(void* const* d_in, const int* in_sizes, int n_in,
                              void* d_out, int out_size) {
    const float* x  = (const float*)d_in[0];
    const int*   ei = (const int*)  d_in[1];
    const float* W1 = (const float*)d_in[2];
    const float* b1 = (const float*)d_in[3];
    const float* W2 = (const float*)d_in[4];
    const float* b2 = (const float*)d_in[5];

    float* out = (float*)d_out;
    float* hid = (float*)d_out + (size_t)NNODES * DIM;

    static bool attr_set = false;
    if (!attr_set) {
        cudaFuncSetAttribute(gemm_kernel,
                             cudaFuncAttributeMaxDynamicSharedMemorySize,
                             (DIM * DIM + DIM * 64) * (int)sizeof(float));
        attr_set = true;
    }

    float* agg;
    cudaGetSymbolAddress((void**)&agg, g_agg);

    const int nb_nodes = (NNODES + 255) / 256;
    const int nb_edges = (NEDGES + 255) / 256;
    const int nb_agg   = (NNODES * 32 + 255) / 256;   // 1 warp/node
    const int nb_gemm  = (NNODES + 63) / 64;
    const int smem     = (DIM * DIM + DIM * 64) * (int)sizeof(float);

    // ---- CSR build (g_deg arrives zeroed: static init / restored by fill) ----
    hist_kernel<<<nb_edges, 256>>>(ei);
    scan1_kernel<<<NBLK, SCANB>>>();
    scan2_kernel<<<1, 128>>>();
    scan3_kernel<<<nb_nodes, 256>>>();
    fill_kernel<<<nb_edges, 256>>>(ei);

    // ---- Layer 1 ----
    agg_kernel<<<nb_agg, 256>>>(x);
    gemm_kernel<<<nb_gemm, 256, smem>>>(agg, W1, b1, hid);

    // ---- Layer 2 ----
    agg_kernel<<<nb_agg, 256>>>(hid);
    gemm_kernel<<<nb_gemm, 256, smem>>>(agg, W2, b2, out);
}

// round 9
// speedup vs baseline: 1.5464x; 1.5464x over previous
#include <cuda_runtime.h>
#include <cuda_bf16.h>
#include <cstdint>

#define NNODES 100000
#define NEDGES 1600000
#define DIM    128
#define SCANB  1024
#define NBLK   ((NNODES + SCANB - 1) / SCANB)   // 98
#define SWROW  129                              // smem row stride (mod 32 == 1)

typedef unsigned long long u64;

// ---------------- scratch (alloc-free rule: __device__ globals) -------------
// g_deg: zero-initialized at module load; fill_kernel re-zeroes it each call.
__device__ float g_agg[(size_t)NNODES * DIM];
__device__ int   g_deg[NNODES];
__device__ int   g_incl[NNODES];
__device__ int   g_off[NNODES + 1];
__device__ int   g_cur[NNODES];
__device__ int   g_csr[NEDGES];
__device__ int   g_bsum[128];
__device__ int   g_bofs[128];

// ---------------------------------------------------------------------------
// packed fp32x2 helpers
// ---------------------------------------------------------------------------
__device__ __forceinline__ u64 ffma2(u64 a, u64 b, u64 c) {
    u64 d;
    asm("fma.rn.f32x2 %0, %1, %2, %3;" : "=l"(d) : "l"(a), "l"(b), "l"(c));
    return d;
}
__device__ __forceinline__ u64 pk2(float lo, float hi) {
    u64 r;
    asm("mov.b64 %0, {%1, %2};" : "=l"(r) : "f"(lo), "f"(hi));
    return r;
}

// ---------------------------------------------------------------------------
// CSR build
// ---------------------------------------------------------------------------
__global__ void hist_kernel(const int* __restrict__ ei) {
    int e = blockIdx.x * blockDim.x + threadIdx.x;
    if (e < NEDGES) atomicAdd(&g_deg[__ldg(ei + NEDGES + e)], 1);
}

__global__ void scan1_kernel() {
    __shared__ int sm[SCANB];
    int i = blockIdx.x * SCANB + threadIdx.x;
    int v = (i < NNODES) ? g_deg[i] : 0;
    sm[threadIdx.x] = v;
    __syncthreads();
#pragma unroll
    for (int ofs = 1; ofs < SCANB; ofs <<= 1) {
        int t = (threadIdx.x >= ofs) ? sm[threadIdx.x - ofs] : 0;
        __syncthreads();
        sm[threadIdx.x] += t;
        __syncthreads();
    }
    if (i < NNODES) g_incl[i] = sm[threadIdx.x];
    if (threadIdx.x == SCANB - 1) g_bsum[blockIdx.x] = sm[SCANB - 1];
}

__global__ void scan2_kernel() {
    __shared__ int sm[128];
    int t = threadIdx.x;
    int v = (t < NBLK) ? g_bsum[t] : 0;
    sm[t] = v;
    __syncthreads();
#pragma unroll
    for (int ofs = 1; ofs < 128; ofs <<= 1) {
        int u = (t >= ofs) ? sm[t - ofs] : 0;
        __syncthreads();
        sm[t] += u;
        __syncthreads();
    }
    if (t < NBLK) g_bofs[t] = sm[t] - v;    // exclusive
}

__global__ void scan3_kernel() {
    int i = blockIdx.x * blockDim.x + threadIdx.x;
    if (i < NNODES) {
        int off = g_incl[i] - g_deg[i] + g_bofs[i >> 10];
        g_off[i] = off;
        g_cur[i] = off;
    }
    if (i == 0) g_off[NNODES] = NEDGES;
}

__global__ void fill_kernel(const int* __restrict__ ei) {
    int e = blockIdx.x * blockDim.x + threadIdx.x;
    if (e < NEDGES) {
        int dst = __ldg(ei + NEDGES + e);
        int p = atomicAdd(&g_cur[dst], 1);
        g_csr[p] = __ldg(ei + e);
    }
    if (e < NNODES) g_deg[e] = 0;   // restore invariant for next replay
}

// ---------------------------------------------------------------------------
// Aggregation (R6 form — measured best): one warp per destination node,
// lane l owns dims [4l, 4l+4). acc = x_i + sum_j x_j. Zero atomics.
// ---------------------------------------------------------------------------
__global__ __launch_bounds__(256)
void agg_kernel(const float* __restrict__ x) {
    int w    = (blockIdx.x * blockDim.x + threadIdx.x) >> 5;
    int lane = threadIdx.x & 31;
    if (w >= NNODES) return;

    const float4* X = reinterpret_cast<const float4*>(x);
    int s = g_off[w];
    int e = g_off[w + 1];

    float4 acc = __ldg(X + (size_t)w * 32 + lane);

    for (int base = s; base < e; base += 32) {
        int idx = base + lane;
        int my  = (idx < e) ? __ldg(g_csr + idx) : 0;
        int nv  = min(32, e - base);
#pragma unroll 4
        for (int j = 0; j < nv; ++j) {
            int src  = __shfl_sync(0xffffffffu, my, j);
            float4 v = __ldg(X + (size_t)src * 32 + lane);
            acc.x += v.x; acc.y += v.y; acc.z += v.z; acc.w += v.w;
        }
    }
    reinterpret_cast<float4*>(g_agg)[(size_t)w * 32 + lane] = acc;
}

// ---------------------------------------------------------------------------
// GEMM: out[n][o] = bias[o] + sum_k H[n][k] * W[o][k]
// 128 threads; tile 64 nodes x 128 outs; 8x8 register tile per thread.
// Smem holds W and H UNtransposed with row stride 129 (bank-rotating):
//   - W reads: warp has 4 distinct tx -> 4 banks, 8-lane broadcast: conflict-free
//   - H reads: 8 distinct ty -> <=2-way conflict
//   - fill writes: <=4-way (vs 32-way in the transpose scheme)
// Inner loop: 16 scalar LDS + 32 FFMA2 -> FMA-pipe-bound.
// ---------------------------------------------------------------------------
__global__ __launch_bounds__(128, 2)
void gemm_kernel(const float* __restrict__ H,
                 const float* __restrict__ W,
                 const float* __restrict__ bias,
                 float* __restrict__ out) {
    extern __shared__ float smf[];
    float* Ws = smf;                   // [128][SWROW]
    float* Hs = smf + DIM * SWROW;     // [64][SWROW]

    const int tid   = threadIdx.x;
    const int node0 = blockIdx.x * 64;

    // Fill W tile: 4096 float4s, 32 iters. Per warp: o const, k4 = lane.
    for (int i = tid; i < DIM * DIM / 4; i += 128) {
        int o  = i >> 5;
        int k4 = (i & 31) << 2;
        float4 w = __ldg(reinterpret_cast<const float4*>(W) + i);
        float* p = Ws + o * SWROW + k4;
        p[0] = w.x; p[1] = w.y; p[2] = w.z; p[3] = w.w;
    }
    // Fill H tile: 2048 float4s, 16 iters.
    for (int i = tid; i < 64 * DIM / 4; i += 128) {
        int n  = i >> 5;
        int k4 = (i & 31) << 2;
        int node = node0 + n;
        float4 h = make_float4(0.f, 0.f, 0.f, 0.f);
        if (node < NNODES)
            h = __ldg(reinterpret_cast<const float4*>(H) + (size_t)node * 32 + (k4 >> 2));
        float* p = Hs + n * SWROW + k4;
        p[0] = h.x; p[1] = h.y; p[2] = h.z; p[3] = h.w;
    }
    __syncthreads();

    const int tx = tid >> 3;      // 16 o-groups of 8
    const int ty = tid & 7;       // 8 n-groups of 8
    const int o0 = tx * 8;
    const int n0 = ty * 8;

    const float* Wb = Ws + o0 * SWROW;
    const float* Hb = Hs + n0 * SWROW;

    // acc[i][j]: packed outputs (o0+2j, o0+2j+1) for node n0+i
    u64 acc[8][4];
    {
        float4 b0 = __ldg(reinterpret_cast<const float4*>(bias + o0));
        float4 b1 = __ldg(reinterpret_cast<const float4*>(bias + o0 + 4));
        u64 bp[4] = { pk2(b0.x, b0.y), pk2(b0.z, b0.w),
                      pk2(b1.x, b1.y), pk2(b1.z, b1.w) };
#pragma unroll
        for (int i = 0; i < 8; ++i)
#pragma unroll
            for (int j = 0; j < 4; ++j) acc[i][j] = bp[j];
    }

#pragma unroll 4
    for (int k = 0; k < DIM; ++k) {
        float w[8], h[8];
#pragma unroll
        for (int i = 0; i < 8; ++i) w[i] = Wb[i * SWROW + k];
#pragma unroll
        for (int i = 0; i < 8; ++i) h[i] = Hb[i * SWROW + k];
        u64 wp[4] = { pk2(w[0], w[1]), pk2(w[2], w[3]),
                      pk2(w[4], w[5]), pk2(w[6], w[7]) };
#pragma unroll
        for (int i = 0; i < 8; ++i) {
            u64 hd = pk2(h[i], h[i]);
#pragma unroll
            for (int j = 0; j < 4; ++j)
                acc[i][j] = ffma2(hd, wp[j], acc[i][j]);
        }
    }

#pragma unroll
    for (int i = 0; i < 8; ++i) {
        int node = node0 + n0 + i;
        if (node < NNODES) {
            ulonglong2* orow = reinterpret_cast<ulonglong2*>(out + (size_t)node * DIM + o0);
            orow[0] = make_ulonglong2(acc[i][0], acc[i][1]);
            orow[1] = make_ulonglong2(acc[i][2], acc[i][3]);
        }
    }
}

// ---------------------------------------------------------------------------
// Launch. Output tuple (out, hid): d_out[0:N*D)=out, d_out[N*D:2N*D)=hid.
// ---------------------------------------------------------------------------
extern "C" void kernel_launch(void* const* d_in, const int* in_sizes, int n_in,
                              void* d_out, int out_size) {
    const float* x  = (const float*)d_in[0];
    const int*   ei = (const int*)  d_in[1];
    const float* W1 = (const float*)d_in[2];
    const float* b1 = (const float*)d_in[3];
    const float* W2 = (const float*)d_in[4];
    const float* b2 = (const float*)d_in[5];

    float* out = (float*)d_out;
    float* hid = (float*)d_out + (size_t)NNODES * DIM;

    const int smem = (DIM + 64) * SWROW * (int)sizeof(float);   // 99072 B

    static bool attr_set = false;
    if (!attr_set) {
        cudaFuncSetAttribute(gemm_kernel,
                             cudaFuncAttributeMaxDynamicSharedMemorySize, smem);
        attr_set = true;
    }

    float* agg;
    cudaGetSymbolAddress((void**)&agg, g_agg);

    const int nb_nodes = (NNODES + 255) / 256;
    const int nb_edges = (NEDGES + 255) / 256;
    const int nb_agg   = (NNODES * 32 + 255) / 256;   // 1 warp/node
    const int nb_gemm  = (NNODES + 63) / 64;

    // ---- CSR build (g_deg arrives zeroed: static init / restored by fill) ----
    hist_kernel<<<nb_edges, 256>>>(ei);
    scan1_kernel<<<NBLK, SCANB>>>();
    scan2_kernel<<<1, 128>>>();
    scan3_kernel<<<nb_nodes, 256>>>();
    fill_kernel<<<nb_edges, 256>>>(ei);

    // ---- Layer 1 ----
    agg_kernel<<<nb_agg, 256>>>(x);
    gemm_kernel<<<nb_gemm, 128, smem>>>(agg, W1, b1, hid);

    // ---- Layer 2 ----
    agg_kernel<<<nb_agg, 256>>>(hid);
    gemm_kernel<<<nb_gemm, 128, smem>>>(agg, W2, b2, out);
}